// round 13
// baseline (speedup 1.0000x reference)
#include <cuda_runtime.h>
#include <math.h>

#define NCTA   128
#define NTHR   512
#define NWARP  16
#define TSTEPS 1000
#define BB     32
#define NN0    256
#define NN1    512
#define GG     4
#define NSPLIT 16
#define NBARS  1000ULL            // 1 initial + 999 inter-step — EXACT
#define BARM   (NBARS * (unsigned long long)NCTA)

typedef unsigned long long u64;

// Cross-step exchange buffers (ping-pong), layout [neuron][batch] (128B rows),
// plus the monotonic grid-barrier counter.
__device__ float g_s0buf[2][NN0 * BB];
__device__ float g_spbuf[2][NN1 * BB];
__device__ unsigned long long g_arrive;

// ---- f32x2 helpers ----
__device__ __forceinline__ u64 dup2(float a) {
    u64 r; asm("mov.b64 %0, {%1,%1};" : "=l"(r) : "f"(a)); return r;
}
__device__ __forceinline__ u64 ffma2(u64 a, u64 b, u64 c) {
    u64 d; asm("fma.rn.f32x2 %0, %1, %2, %3;" : "=l"(d) : "l"(a), "l"(b), "l"(c)); return d;
}
__device__ __forceinline__ u64 add2(u64 a, u64 b) {
    u64 d; asm("add.rn.f32x2 %0, %1, %2;" : "=l"(d) : "l"(a), "l"(b)); return d;
}
__device__ __forceinline__ u64 shfl_xor_u64(u64 v, int m) {
    unsigned lo = (unsigned)v, hi = (unsigned)(v >> 32);
    lo = __shfl_xor_sync(0xffffffffu, lo, m);
    hi = __shfl_xor_sync(0xffffffffu, hi, m);
    return ((u64)hi << 32) | lo;
}

__global__ void __launch_bounds__(NTHR, 1)
rsnn_kernel(const float* __restrict__ inp,
            const float* __restrict__ W1,
            const float* __restrict__ Wr,
            float* __restrict__ out)
{
    __shared__ u64   wp1d[NN0 * GG];              // 8 KB  dup-packed (w,w) [n][g]
    __shared__ u64   wprd[NN1 * GG];              // 16 KB dup-packed (w,w) [n][g]
    __shared__ float psum1[NSPLIT * GG * BB];     // 8 KB
    __shared__ float psum2[NSPLIT * GG * BB];     // 8 KB
    __shared__ float sta[BB * GG];                // staged spa [b][g]
    __shared__ float stb[BB * GG];                // staged spb [b][g]
    __shared__ unsigned long long sh_base;

    const int tid   = threadIdx.x;
    const int cta   = blockIdx.x;
    const int ws    = tid >> 5;
    const int lane  = tid & 31;
    const int ng    = lane >> 3;      // 0..3 : n sub-slice within warp
    const int bg    = lane & 7;       // 0..7 : batch group (4 batches)
    const int mbase = cta * GG;

    // ---- GLIF constants ----
    const float CID = 0.95f;
    const float CIA = 0.05f;
    const float CVD = 0.99f;
    const float CVA = (float)(0.05 * (1.0 / 5.0) * (1.0 / 9.43));
    const float TH  = (float)(10.0 * 1.0986122886681098);
    const float AD0 = (float)(1.0 - 0.05 * 0.003);
    const float AD1 = (float)(1.0 - 0.05 * 0.1);
    const float AA0 = (float)(-9.18 * 0.05);
    const float AA1 = (float)(-198.94 * 0.05);

    // ---- one-time weight prepack: wpXd[n*4+g] = dup(W[mbase+g][n]) ----
    for (int i = tid; i < NN0 * GG; i += NTHR)
        wp1d[i] = dup2(W1[(mbase + (i & 3)) * NN0 + (i >> 2)]);
    for (int i = tid; i < NN1 * GG; i += NTHR)
        wprd[i] = dup2(Wr[(mbase + (i & 3)) * NN1 + (i >> 2)]);

    // ---- launch-consistent barrier base ----
    if (tid == 0) {
        unsigned long long g = *(volatile unsigned long long*)&g_arrive;
        sh_base = (g / BARM) * BARM;
    }

    // ---- zero the parity-1 buffers (initial delayed state) ----
    {
        const int per   = (NN0 * BB + NN1 * BB) / NCTA;  // 192
        const int start = cta * per;
        for (int i = tid; i < per; i += NTHR) {
            int idx = start + i;
            if (idx < NN0 * BB) g_s0buf[1][idx] = 0.0f;
            else                g_spbuf[1][idx - NN0 * BB] = 0.0f;
        }
    }
    __syncthreads();
    const unsigned long long base = sh_base;

    // ---- recurrent state in registers ----
    float V1 = 0.f, I1 = 0.f, A10 = 0.f, A11 = 0.f;   // layer-1 (tid < 128)
    float V0 = 0.f, I0 = 0.f, A00 = 0.f, A01 = 0.f;   // layer-0 (tid 128..191)

    const int rg = tid >> 5;          // reducer g (tid < 128)
    const int rb = tid & 31;          // reducer b

    const bool isl0 = (tid >= 128 && tid < 192);
    const int l0id = cta * 64 + (tid - 128);
    const int l0b  = l0id >> 8;
    const int l0n  = l0id & 255;

    const int nb1 = ws * (NN0 / NWARP);   // 16-wide n slice (GEMM1)
    const int nb2 = ws * (NN1 / NWARP);   // 32-wide n slice (GEMM2)

    // ---- initial barrier (arrival #1) ----
    if (tid == 0) {
        __threadfence();
        atomicAdd(&g_arrive, 1ULL);
        while (*(volatile unsigned long long*)&g_arrive < base + NCTA) { }
        __threadfence();
    }
    // prefetch layer-0 input for t = 0 while barrier settles
    float x0 = 0.0f;
    if (isl0) x0 = __ldg(&inp[l0b * NN0 + l0n]);
    __syncthreads();

    for (int t = 0; t < TSTEPS; ++t) {
        const float* __restrict__ s0r = g_s0buf[(t & 1) ^ 1];
        const float* __restrict__ spr = g_spbuf[(t & 1) ^ 1];

        // ---- GEMM phase: thread computes 4g x 4b tile; zero-MOV inner loop ----
        u64 acc1[8], acc2[8];
#pragma unroll
        for (int i = 0; i < 8; ++i) { acc1[i] = 0ULL; acc2[i] = 0ULL; }

#pragma unroll
        for (int k = 0; k < 4; ++k) {          // GEMM1: n = nb1 + k*4 + ng
            const int n = nb1 + k * 4 + ng;
            ulonglong2 xv = __ldcg((const ulonglong2*)(s0r + n * BB + bg * 4));
            ulonglong2 wa = *(const ulonglong2*)&wp1d[n * 4];       // (w0,w0),(w1,w1)
            ulonglong2 wb = *(const ulonglong2*)&wp1d[n * 4 + 2];   // (w2,w2),(w3,w3)
            acc1[0] = ffma2(wa.x, xv.x, acc1[0]); acc1[1] = ffma2(wa.x, xv.y, acc1[1]);
            acc1[2] = ffma2(wa.y, xv.x, acc1[2]); acc1[3] = ffma2(wa.y, xv.y, acc1[3]);
            acc1[4] = ffma2(wb.x, xv.x, acc1[4]); acc1[5] = ffma2(wb.x, xv.y, acc1[5]);
            acc1[6] = ffma2(wb.y, xv.x, acc1[6]); acc1[7] = ffma2(wb.y, xv.y, acc1[7]);
        }
#pragma unroll
        for (int k = 0; k < 8; ++k) {          // GEMM2: n = nb2 + k*4 + ng
            const int n = nb2 + k * 4 + ng;
            ulonglong2 xv = __ldcg((const ulonglong2*)(spr + n * BB + bg * 4));
            ulonglong2 wa = *(const ulonglong2*)&wprd[n * 4];
            ulonglong2 wb = *(const ulonglong2*)&wprd[n * 4 + 2];
            acc2[0] = ffma2(wa.x, xv.x, acc2[0]); acc2[1] = ffma2(wa.x, xv.y, acc2[1]);
            acc2[2] = ffma2(wa.y, xv.x, acc2[2]); acc2[3] = ffma2(wa.y, xv.y, acc2[3]);
            acc2[4] = ffma2(wb.x, xv.x, acc2[4]); acc2[5] = ffma2(wb.x, xv.y, acc2[5]);
            acc2[6] = ffma2(wb.y, xv.x, acc2[6]); acc2[7] = ffma2(wb.y, xv.y, acc2[7]);
        }

        // ---- two butterfly levels over ng (xor 8, xor 16) ----
#pragma unroll
        for (int i = 0; i < 8; ++i) {
            acc1[i] = add2(acc1[i], shfl_xor_u64(acc1[i], 8));
            acc2[i] = add2(acc2[i], shfl_xor_u64(acc2[i], 8));
            acc1[i] = add2(acc1[i], shfl_xor_u64(acc1[i], 16));
            acc2[i] = add2(acc2[i], shfl_xor_u64(acc2[i], 16));
        }

        // ---- psum stores: 16 splits, direct STS.64 (no unpack MOVs) ----
        if (ng == 0) {
            const int sbase = ws * (GG * BB) + bg * 4;
#pragma unroll
            for (int g = 0; g < GG; ++g) {
                *(u64*)&psum1[sbase + g * BB]     = acc1[g * 2];
                *(u64*)&psum1[sbase + g * BB + 2] = acc1[g * 2 + 1];
                *(u64*)&psum2[sbase + g * BB]     = acc2[g * 2];
                *(u64*)&psum2[sbase + g * BB + 2] = acc2[g * 2 + 1];
            }
        }
        __syncthreads();

        if (tid < 128) {
            // reduce 16 splits for (g=rg, b=rb), then both GLIF calls
            float h1a = 0.f, h1b = 0.f, h2a = 0.f, h2b = 0.f;
#pragma unroll
            for (int s = 0; s < NSPLIT; s += 2) {
                h1a += psum1[s * (GG * BB) + rg * BB + rb];
                h1b += psum1[(s + 1) * (GG * BB) + rg * BB + rb];
                h2a += psum2[s * (GG * BB) + rg * BB + rb];
                h2b += psum2[(s + 1) * (GG * BB) + rg * BB + rb];
            }
            const float h1 = h1a + h1b, h2 = h2a + h2b;

            // call A (feedforward) -> sp_a
            I1 = I1 * CID + CIA * h1;
            V1 = V1 * CVD + CVA * (I1 + A10 + A11);
            float spa = 20.0f / (1.0f + __expf((TH - V1) * 0.1f));
            A10 = A10 * AD0 + AA0 * spa;
            A11 = A11 * AD1 + AA1 * spa;
            // call B (recurrent) -> sp_b
            I1 = I1 * CID + CIA * h2;
            V1 = V1 * CVD + CVA * (I1 + A10 + A11);
            float spb = 20.0f / (1.0f + __expf((TH - V1) * 0.1f));
            A10 = A10 * AD0 + AA0 * spb;
            A11 = A11 * AD1 + AA1 * spb;

            g_spbuf[t & 1][(mbase + rg) * BB + rb] = spb;   // exchange (critical)
            sta[rb * GG + rg] = spa;
            stb[rb * GG + rg] = spb;
        } else if (isl0) {
            // layer-0 GLIF on prefetched raw input
            I0 = I0 * CID + CIA * x0;
            V0 = V0 * CVD + CVA * (I0 + A00 + A01);
            float s = 20.0f / (1.0f + __expf((TH - V0) * 0.1f));
            A00 = A00 * AD0 + AA0 * s;
            A01 = A01 * AD1 + AA1 * s;
            g_s0buf[t & 1][l0n * BB + l0b] = s;             // exchange (critical)
        }

        // ================= split-phase grid barrier =================
        __syncthreads();                      // exchanges + staging complete
        if (tid == 0 && t + 1 < TSTEPS) {     // ARRIVE (999 of these; none at t=999)
            __threadfence();
            atomicAdd(&g_arrive, 1ULL);
        }

        // ---- window work (no cross-CTA consumer this step) ----
        if (ws == 0) {
            *(float4*)&out[(2 * t) * (BB * NN1) + lane * NN1 + mbase] =
                *(const float4*)&sta[lane * GG];
        } else if (ws == 1) {
            *(float4*)&out[(2 * t + 1) * (BB * NN1) + lane * NN1 + mbase] =
                *(const float4*)&stb[lane * GG];
        }
        if (isl0 && t + 1 < TSTEPS)
            x0 = __ldg(&inp[(t + 1) * (BB * NN0) + l0b * NN0 + l0n]);

        if (t + 1 < TSTEPS) {
            if (tid == 0) {                   // WAIT
                const unsigned long long tgt =
                    base + (unsigned long long)(t + 2) * NCTA;
                while (*(volatile unsigned long long*)&g_arrive < tgt) { }
                __threadfence();
            }
            __syncthreads();                  // release
        }
    }
}

extern "C" void kernel_launch(void* const* d_in, const int* in_sizes, int n_in,
                              void* d_out, int out_size) {
    const float* inp = (const float*)d_in[0];
    const float* W1  = (const float*)d_in[1];
    const float* Wr  = (const float*)d_in[2];
    float* out       = (float*)d_out;
    rsnn_kernel<<<NCTA, NTHR>>>(inp, W1, Wr, out);
}